// round 3
// baseline (speedup 1.0000x reference)
#include <cuda_runtime.h>
#include <cstdint>

#define N_NODES 50000
#define N_EDGES 800000
#define DIM     128
#define N_LAYERS 3
#define N_GRAPHS 128
#define TOT_E   (N_EDGES + N_NODES)   // edges + self loops
#define XS_COLS (DIM * N_LAYERS)      // 384
#define POOL_ELEMS (N_GRAPHS * XS_COLS)

// ---------------- scratch (device globals; no allocation allowed) ----------
__device__ int   g_deg[N_NODES];
__device__ int   g_fill[N_NODES];
__device__ int   g_rowptr[N_NODES + 1];
__device__ int   g_colidx[TOT_E];
__device__ float g_dinv[N_NODES];
__device__ float g_t[(size_t)N_NODES * DIM];   // dinv-scaled GEMM output
__device__ int   g_goff[N_GRAPHS + 1];

// ---------------- CSR build ------------------------------------------------
__global__ void init_kernel() {
    int n = blockIdx.x * blockDim.x + threadIdx.x;
    if (n < N_NODES) { g_deg[n] = 1; g_fill[n] = 0; }   // self loop counts 1
}

__global__ void edge_deg_kernel(const int* __restrict__ ei) {
    int e = blockIdx.x * blockDim.x + threadIdx.x;
    if (e < N_EDGES) {
        int dst = ei[N_EDGES + e];
        atomicAdd(&g_deg[dst], 1);
    }
}

__global__ void dinv_kernel() {
    int n = blockIdx.x * blockDim.x + threadIdx.x;
    if (n < N_NODES) g_dinv[n] = rsqrtf((float)g_deg[n]);
}

// single-block exclusive scan of g_deg -> g_rowptr (N+1 entries)
__global__ void scan_kernel() {
    __shared__ int sh[1024];
    const int t = threadIdx.x;
    const int C = (N_NODES + 1 + 1023) / 1024;   // 49
    int begin = t * C;
    int endi  = min(begin + C, N_NODES + 1);
    int s = 0;
    for (int i = begin; i < endi; i++) s += (i < N_NODES) ? g_deg[i] : 0;
    sh[t] = s;
    __syncthreads();
    // Hillis–Steele inclusive scan
    for (int off = 1; off < 1024; off <<= 1) {
        int v = (t >= off) ? sh[t - off] : 0;
        __syncthreads();
        sh[t] += v;
        __syncthreads();
    }
    int run = (t == 0) ? 0 : sh[t - 1];
    for (int i = begin; i < endi; i++) {
        g_rowptr[i] = run;
        if (i < N_NODES) run += g_deg[i];
    }
}

__global__ void fill_kernel(const int* __restrict__ ei) {
    int idx = blockIdx.x * blockDim.x + threadIdx.x;
    if (idx < N_NODES) {                       // self loop
        int pos = g_rowptr[idx] + atomicAdd(&g_fill[idx], 1);
        g_colidx[pos] = idx;
    } else if (idx < N_NODES + N_EDGES) {
        int e = idx - N_NODES;
        int src = ei[e];
        int dst = ei[N_EDGES + e];
        int pos = g_rowptr[dst] + atomicAdd(&g_fill[dst], 1);
        g_colidx[pos] = src;
    }
}

// graph segment offsets via binary search over sorted batch
__global__ void goff_kernel(const int* __restrict__ batch) {
    int g = threadIdx.x;
    if (g > N_GRAPHS) return;
    int lo = 0, hi = N_NODES;
    while (lo < hi) {
        int mid = (lo + hi) >> 1;
        if (batch[mid] < g) lo = mid + 1; else hi = mid;
    }
    g_goff[g] = lo;
}

// ---------------- GEMM: T[n,:] = dinv[n] * (A[n,:] @ W) --------------------
// block: 128 rows x 128 cols, 256 threads, 8x8 per-thread tile, BK=16
__global__ __launch_bounds__(256, 2)
void gemm_scale_kernel(const float* __restrict__ A, int lda,
                       const float* __restrict__ W) {
    __shared__ float As[16][132];
    __shared__ float Ws[16][128];
    const int brow = blockIdx.x * 128;
    const int t  = threadIdx.x;
    const int tx = t & 15;     // col group
    const int ty = t >> 4;     // row group
    float acc[8][8];
#pragma unroll
    for (int i = 0; i < 8; i++)
#pragma unroll
        for (int j = 0; j < 8; j++) acc[i][j] = 0.f;

    for (int kc = 0; kc < DIM; kc += 16) {
        // A tile: 128 rows x 16 k, transposed into As[k][row]
#pragma unroll
        for (int i = 0; i < 2; i++) {
            int lin = t + i * 256;          // 0..511
            int row = lin >> 2;             // 0..127
            int kg  = lin & 3;
            float4 v = make_float4(0.f, 0.f, 0.f, 0.f);
            int gr = brow + row;
            if (gr < N_NODES)
                v = *(const float4*)&A[(size_t)gr * lda + kc + kg * 4];
            As[kg * 4 + 0][row] = v.x;
            As[kg * 4 + 1][row] = v.y;
            As[kg * 4 + 2][row] = v.z;
            As[kg * 4 + 3][row] = v.w;
        }
        // W tile: 16 k-rows x 128 cols
#pragma unroll
        for (int i = 0; i < 2; i++) {
            int lin = t + i * 256;
            int kr = lin >> 5;              // 0..15
            int c4 = lin & 31;
            *(float4*)&Ws[kr][c4 * 4] =
                *(const float4*)&W[(kc + kr) * DIM + c4 * 4];
        }
        __syncthreads();
#pragma unroll
        for (int kk = 0; kk < 16; kk++) {
            float a[8], w[8];
#pragma unroll
            for (int i = 0; i < 8; i++) a[i] = As[kk][ty * 8 + i];
#pragma unroll
            for (int j = 0; j < 8; j++) w[j] = Ws[kk][tx * 8 + j];
#pragma unroll
            for (int i = 0; i < 8; i++)
#pragma unroll
                for (int j = 0; j < 8; j++)
                    acc[i][j] = fmaf(a[i], w[j], acc[i][j]);
        }
        __syncthreads();
    }
    // epilogue: scale by dinv[row], store to g_t
#pragma unroll
    for (int i = 0; i < 8; i++) {
        int gr = brow + ty * 8 + i;
        if (gr < N_NODES) {
            float s = g_dinv[gr];
#pragma unroll
            for (int j = 0; j < 8; j += 4) {
                float4 o;
                o.x = acc[i][j + 0] * s;
                o.y = acc[i][j + 1] * s;
                o.z = acc[i][j + 2] * s;
                o.w = acc[i][j + 3] * s;
                *(float4*)&g_t[(size_t)gr * DIM + tx * 8 + j] = o;
            }
        }
    }
}

// ---------------- SpMM: out[r,:] = relu(dinv[r]*sum_{s in row r} T[s,:] + b)
// one warp per destination row; out has row stride XS_COLS (writes layer slice)
__global__ void spmm_kernel(const float* __restrict__ bias,
                            float* __restrict__ out) {
    int w    = (blockIdx.x * blockDim.x + threadIdx.x) >> 5;
    int lane = threadIdx.x & 31;
    if (w >= N_NODES) return;
    int e = g_rowptr[w], end = g_rowptr[w + 1];
    float4 acc = make_float4(0.f, 0.f, 0.f, 0.f);
    for (; e + 1 < end; e += 2) {
        int s0 = g_colidx[e];
        int s1 = g_colidx[e + 1];
        float4 v0 = *(const float4*)&g_t[(size_t)s0 * DIM + lane * 4];
        float4 v1 = *(const float4*)&g_t[(size_t)s1 * DIM + lane * 4];
        acc.x += v0.x + v1.x;
        acc.y += v0.y + v1.y;
        acc.z += v0.z + v1.z;
        acc.w += v0.w + v1.w;
    }
    if (e < end) {
        int s0 = g_colidx[e];
        float4 v0 = *(const float4*)&g_t[(size_t)s0 * DIM + lane * 4];
        acc.x += v0.x; acc.y += v0.y; acc.z += v0.z; acc.w += v0.w;
    }
    float dv = g_dinv[w];
    float4 bb = *(const float4*)&bias[lane * 4];
    float4 o;
    o.x = fmaxf(fmaf(acc.x, dv, bb.x), 0.f);
    o.y = fmaxf(fmaf(acc.y, dv, bb.y), 0.f);
    o.z = fmaxf(fmaf(acc.z, dv, bb.z), 0.f);
    o.w = fmaxf(fmaf(acc.w, dv, bb.w), 0.f);
    *(float4*)&out[(size_t)w * XS_COLS + lane * 4] = o;
}

// ---------------- pooling: block per graph, 384 threads (one per feature) --
__global__ void pool_kernel(const float* __restrict__ xs,
                            float* __restrict__ out_pool) {
    int g = blockIdx.x;
    int f = threadIdx.x;      // 0..383
    int s = g_goff[g], e = g_goff[g + 1];
    float sum = 0.f;
    for (int n = s; n < e; n++)
        sum += xs[(size_t)n * XS_COLS + f];
    float cnt = (float)max(e - s, 1);
    out_pool[(size_t)g * XS_COLS + f] = sum / cnt;
}

// ---------------- launch ---------------------------------------------------
extern "C" void kernel_launch(void* const* d_in, const int* in_sizes, int n_in,
                              void* d_out, int out_size) {
    const float* x     = (const float*)d_in[0];
    const int*   ei    = (const int*)d_in[1];     // int32: JAX x64 disabled
    const int*   batch = (const int*)d_in[2];     // int32
    const float* W[3] = { (const float*)d_in[3], (const float*)d_in[5],
                          (const float*)d_in[7] };
    const float* B[3] = { (const float*)d_in[4], (const float*)d_in[6],
                          (const float*)d_in[8] };
    float* out_pool = (float*)d_out;
    float* out_xs   = (float*)d_out + POOL_ELEMS;

    // CSR + norm build
    init_kernel<<<(N_NODES + 255) / 256, 256>>>();
    edge_deg_kernel<<<(N_EDGES + 255) / 256, 256>>>(ei);
    scan_kernel<<<1, 1024>>>();
    dinv_kernel<<<(N_NODES + 255) / 256, 256>>>();
    fill_kernel<<<(TOT_E + 255) / 256, 256>>>(ei);
    goff_kernel<<<1, 256>>>(batch);

    const int gemm_blocks = (N_NODES + 127) / 128;
    const int spmm_blocks = (N_NODES * 32 + 255) / 256;

    for (int l = 0; l < N_LAYERS; l++) {
        const float* in  = (l == 0) ? x : (out_xs + (size_t)(l - 1) * DIM);
        int          lda = (l == 0) ? DIM : XS_COLS;
        gemm_scale_kernel<<<gemm_blocks, 256>>>(in, lda, W[l]);
        spmm_kernel<<<spmm_blocks, 256>>>(B[l], out_xs + (size_t)l * DIM);
    }
    pool_kernel<<<N_GRAPHS, XS_COLS>>>(out_xs, out_pool);
}

// round 4
// speedup vs baseline: 1.1433x; 1.1433x over previous
#include <cuda_runtime.h>
#include <cstdint>

#define N_NODES 50000
#define N_EDGES 800000
#define DIM     128
#define N_LAYERS 3
#define N_GRAPHS 128
#define TOT_E   (N_EDGES + N_NODES)   // edges + self loops
#define XS_COLS (DIM * N_LAYERS)      // 384
#define POOL_ELEMS (N_GRAPHS * XS_COLS)
#define NBLK    196                   // ceil(N_NODES/256)

// ---------------- scratch (device globals; no allocation allowed) ----------
__device__ int   g_deg[N_NODES];
__device__ int   g_fill[N_NODES];
__device__ int   g_rowptr[N_NODES + 1];
__device__ int   g_colidx[TOT_E];
__device__ float g_dinv[N_NODES];
__device__ float g_t[(size_t)N_NODES * DIM];   // GEMM output (unscaled)
__device__ int   g_goff[N_GRAPHS + 1];
__device__ int   g_bsum[NBLK];

// ---------------- packed f32x2 helpers -------------------------------------
__device__ __forceinline__ unsigned long long pack2(float x, float y) {
    unsigned long long r;
    asm("mov.b64 %0, {%1, %2};" : "=l"(r) : "f"(x), "f"(y));
    return r;
}
__device__ __forceinline__ void unpack2(unsigned long long v, float& lo, float& hi) {
    asm("mov.b64 {%0, %1}, %2;" : "=f"(lo), "=f"(hi) : "l"(v));
}
__device__ __forceinline__ void ffma2(unsigned long long& d,
                                      unsigned long long a,
                                      unsigned long long b) {
    asm("fma.rn.f32x2 %0, %1, %2, %0;" : "+l"(d) : "l"(a), "l"(b));
}

// ---------------- CSR build ------------------------------------------------
__global__ void init_kernel() {
    int n = blockIdx.x * blockDim.x + threadIdx.x;
    if (n < N_NODES) { g_deg[n] = 1; g_fill[n] = 0; }   // self loop counts 1
}

__global__ void edge_deg_kernel(const int* __restrict__ ei) {
    int e = blockIdx.x * blockDim.x + threadIdx.x;
    if (e < N_EDGES) atomicAdd(&g_deg[ei[N_EDGES + e]], 1);
}

// phase A: per-block sums of deg
__global__ void scanA_kernel() {
    __shared__ int sh[8];
    int i = blockIdx.x * 256 + threadIdx.x;
    int v = (i < N_NODES) ? g_deg[i] : 0;
#pragma unroll
    for (int o = 16; o; o >>= 1) v += __shfl_down_sync(~0u, v, o);
    if ((threadIdx.x & 31) == 0) sh[threadIdx.x >> 5] = v;
    __syncthreads();
    if (threadIdx.x < 8) {
        int s = sh[threadIdx.x];
#pragma unroll
        for (int o = 4; o; o >>= 1) s += __shfl_down_sync(0xffu, s, o);
        if (threadIdx.x == 0) g_bsum[blockIdx.x] = s;
    }
}

// phase B: scan the 196 block sums (exclusive, in place); also goff bsearch
__global__ void scanB_kernel(const int* __restrict__ batch) {
    __shared__ int sh[256];
    int t = threadIdx.x;
    int v = (t < NBLK) ? g_bsum[t] : 0;
    sh[t] = v;
    __syncthreads();
#pragma unroll
    for (int o = 1; o < 256; o <<= 1) {
        int u = (t >= o) ? sh[t - o] : 0;
        __syncthreads();
        sh[t] += u;
        __syncthreads();
    }
    if (t < NBLK) g_bsum[t] = sh[t] - v;       // exclusive
    if (t == 0)   g_rowptr[N_NODES] = TOT_E;
    if (t <= N_GRAPHS) {                       // graph offsets
        int lo = 0, hi = N_NODES;
        while (lo < hi) {
            int mid = (lo + hi) >> 1;
            if (batch[mid] < t) lo = mid + 1; else hi = mid;
        }
        g_goff[t] = lo;
    }
}

// phase C: intra-block exclusive scan + base -> rowptr; also dinv
__global__ void scanC_kernel() {
    __shared__ int sh[256];
    int t = threadIdx.x;
    int i = blockIdx.x * 256 + t;
    int v = (i < N_NODES) ? g_deg[i] : 0;
    sh[t] = v;
    __syncthreads();
#pragma unroll
    for (int o = 1; o < 256; o <<= 1) {
        int u = (t >= o) ? sh[t - o] : 0;
        __syncthreads();
        sh[t] += u;
        __syncthreads();
    }
    if (i < N_NODES) {
        g_rowptr[i] = sh[t] - v + g_bsum[blockIdx.x];
        g_dinv[i]   = rsqrtf((float)v);
    }
}

__global__ void fill_kernel(const int* __restrict__ ei) {
    int idx = blockIdx.x * blockDim.x + threadIdx.x;
    if (idx < N_NODES) {                       // self loop
        int pos = g_rowptr[idx] + atomicAdd(&g_fill[idx], 1);
        g_colidx[pos] = idx;
    } else if (idx < N_NODES + N_EDGES) {
        int e = idx - N_NODES;
        int src = ei[e];
        int dst = ei[N_EDGES + e];
        int pos = g_rowptr[dst] + atomicAdd(&g_fill[dst], 1);
        g_colidx[pos] = src;
    }
}

// ---------------- GEMM: T[n,:] = A[n,:] @ W  (f32x2 packed FFMA) -----------
// block: 128 rows x 128 cols, 256 threads, 8x8 per-thread tile, BK=16
__global__ __launch_bounds__(256, 2)
void gemm_kernel(const float* __restrict__ A, int lda,
                 const float* __restrict__ W) {
    __shared__ __align__(16) float As[16][132];
    __shared__ __align__(16) float Ws[16][128];
    const int brow = blockIdx.x * 128;
    const int t  = threadIdx.x;
    const int tx = t & 15;     // col group
    const int ty = t >> 4;     // row group
    unsigned long long acc2[8][4];
#pragma unroll
    for (int i = 0; i < 8; i++)
#pragma unroll
        for (int jp = 0; jp < 4; jp++) acc2[i][jp] = 0ull;

    for (int kc = 0; kc < DIM; kc += 16) {
        // A tile: 128 rows x 16 k, transposed into As[k][row]
#pragma unroll
        for (int i = 0; i < 2; i++) {
            int lin = t + i * 256;          // 0..511
            int row = lin >> 2;             // 0..127
            int kg  = lin & 3;
            float4 v = make_float4(0.f, 0.f, 0.f, 0.f);
            int gr = brow + row;
            if (gr < N_NODES)
                v = *(const float4*)&A[(size_t)gr * lda + kc + kg * 4];
            As[kg * 4 + 0][row] = v.x;
            As[kg * 4 + 1][row] = v.y;
            As[kg * 4 + 2][row] = v.z;
            As[kg * 4 + 3][row] = v.w;
        }
        // W tile: 16 k-rows x 128 cols
#pragma unroll
        for (int i = 0; i < 2; i++) {
            int lin = t + i * 256;
            int kr = lin >> 5;              // 0..15
            int c4 = lin & 31;
            *(float4*)&Ws[kr][c4 * 4] =
                *(const float4*)&W[(kc + kr) * DIM + c4 * 4];
        }
        __syncthreads();
#pragma unroll
        for (int kk = 0; kk < 16; kk++) {
            float a[8];
            unsigned long long w2[4];
#pragma unroll
            for (int i = 0; i < 8; i++) a[i] = As[kk][ty * 8 + i];
#pragma unroll
            for (int jp = 0; jp < 4; jp++)
                w2[jp] = *(const unsigned long long*)&Ws[kk][tx * 8 + jp * 2];
#pragma unroll
            for (int i = 0; i < 8; i++) {
                unsigned long long a2 = pack2(a[i], a[i]);
#pragma unroll
                for (int jp = 0; jp < 4; jp++)
                    ffma2(acc2[i][jp], a2, w2[jp]);
            }
        }
        __syncthreads();
    }
    // epilogue: store to g_t (unscaled; dinv applied in SpMM)
#pragma unroll
    for (int i = 0; i < 8; i++) {
        int gr = brow + ty * 8 + i;
        if (gr < N_NODES) {
            float4 o0, o1;
            unpack2(acc2[i][0], o0.x, o0.y);
            unpack2(acc2[i][1], o0.z, o0.w);
            unpack2(acc2[i][2], o1.x, o1.y);
            unpack2(acc2[i][3], o1.z, o1.w);
            *(float4*)&g_t[(size_t)gr * DIM + tx * 8]     = o0;
            *(float4*)&g_t[(size_t)gr * DIM + tx * 8 + 4] = o1;
        }
    }
}

// ---- SpMM: out[r,:] = relu(dinv[r]*sum_{s in row r} dinv[s]*T[s,:] + b) ---
// one warp per destination row; out has row stride XS_COLS
__global__ void spmm_kernel(const float* __restrict__ bias,
                            float* __restrict__ out) {
    int w    = (blockIdx.x * blockDim.x + threadIdx.x) >> 5;
    int lane = threadIdx.x & 31;
    if (w >= N_NODES) return;
    int e = g_rowptr[w], end = g_rowptr[w + 1];
    float4 acc = make_float4(0.f, 0.f, 0.f, 0.f);
    for (; e + 1 < end; e += 2) {
        int s0 = g_colidx[e];
        int s1 = g_colidx[e + 1];
        float d0 = __ldg(&g_dinv[s0]);
        float d1 = __ldg(&g_dinv[s1]);
        float4 v0 = *(const float4*)&g_t[(size_t)s0 * DIM + lane * 4];
        float4 v1 = *(const float4*)&g_t[(size_t)s1 * DIM + lane * 4];
        acc.x = fmaf(v0.x, d0, fmaf(v1.x, d1, acc.x));
        acc.y = fmaf(v0.y, d0, fmaf(v1.y, d1, acc.y));
        acc.z = fmaf(v0.z, d0, fmaf(v1.z, d1, acc.z));
        acc.w = fmaf(v0.w, d0, fmaf(v1.w, d1, acc.w));
    }
    if (e < end) {
        int s0 = g_colidx[e];
        float d0 = __ldg(&g_dinv[s0]);
        float4 v0 = *(const float4*)&g_t[(size_t)s0 * DIM + lane * 4];
        acc.x = fmaf(v0.x, d0, acc.x);
        acc.y = fmaf(v0.y, d0, acc.y);
        acc.z = fmaf(v0.z, d0, acc.z);
        acc.w = fmaf(v0.w, d0, acc.w);
    }
    float dv = g_dinv[w];
    float4 bb = *(const float4*)&bias[lane * 4];
    float4 o;
    o.x = fmaxf(fmaf(acc.x, dv, bb.x), 0.f);
    o.y = fmaxf(fmaf(acc.y, dv, bb.y), 0.f);
    o.z = fmaxf(fmaf(acc.z, dv, bb.z), 0.f);
    o.w = fmaxf(fmaf(acc.w, dv, bb.w), 0.f);
    *(float4*)&out[(size_t)w * XS_COLS + lane * 4] = o;
}

// ---------------- pooling: block per graph, 384 threads (one per feature) --
__global__ void pool_kernel(const float* __restrict__ xs,
                            float* __restrict__ out_pool) {
    int g = blockIdx.x;
    int f = threadIdx.x;      // 0..383
    int s = g_goff[g], e = g_goff[g + 1];
    float sum = 0.f;
    for (int n = s; n < e; n++)
        sum += xs[(size_t)n * XS_COLS + f];
    float cnt = (float)max(e - s, 1);
    out_pool[(size_t)g * XS_COLS + f] = sum / cnt;
}

// ---------------- launch ---------------------------------------------------
extern "C" void kernel_launch(void* const* d_in, const int* in_sizes, int n_in,
                              void* d_out, int out_size) {
    const float* x     = (const float*)d_in[0];
    const int*   ei    = (const int*)d_in[1];     // int32 (JAX x64 disabled)
    const int*   batch = (const int*)d_in[2];     // int32
    const float* W[3] = { (const float*)d_in[3], (const float*)d_in[5],
                          (const float*)d_in[7] };
    const float* B[3] = { (const float*)d_in[4], (const float*)d_in[6],
                          (const float*)d_in[8] };
    float* out_pool = (float*)d_out;
    float* out_xs   = (float*)d_out + POOL_ELEMS;

    static cudaStream_t s2  = nullptr;
    static cudaEvent_t  evF = nullptr, evJ = nullptr;
    if (!s2) {
        cudaStreamCreateWithFlags(&s2, cudaStreamNonBlocking);
        cudaEventCreateWithFlags(&evF, cudaEventDisableTiming);
        cudaEventCreateWithFlags(&evJ, cudaEventDisableTiming);
    }

    const int gemm_blocks = (N_NODES + 127) / 128;           // 391
    const int spmm_blocks = (N_NODES * 32 + 255) / 256;

    // fork: layer-0 GEMM (independent of CSR/dinv) runs on s2
    cudaEventRecord(evF, 0);
    cudaStreamWaitEvent(s2, evF, 0);
    gemm_kernel<<<gemm_blocks, 256, 0, s2>>>(x, DIM, W[0]);

    // CSR + norm build on the capture stream
    init_kernel<<<NBLK, 256>>>();
    edge_deg_kernel<<<(N_EDGES + 255) / 256, 256>>>(ei);
    scanA_kernel<<<NBLK, 256>>>();
    scanB_kernel<<<1, 256>>>(batch);
    scanC_kernel<<<NBLK, 256>>>();
    fill_kernel<<<(TOT_E + 255) / 256, 256>>>(ei);

    // join
    cudaEventRecord(evJ, s2);
    cudaStreamWaitEvent(0, evJ, 0);

    spmm_kernel<<<spmm_blocks, 256>>>(B[0], out_xs);
    gemm_kernel<<<gemm_blocks, 256>>>(out_xs, XS_COLS, W[1]);
    spmm_kernel<<<spmm_blocks, 256>>>(B[1], out_xs + DIM);
    gemm_kernel<<<gemm_blocks, 256>>>(out_xs + DIM, XS_COLS, W[2]);
    spmm_kernel<<<spmm_blocks, 256>>>(B[2], out_xs + 2 * DIM);

    pool_kernel<<<N_GRAPHS, XS_COLS>>>(out_xs, out_pool);
}

// round 6
// speedup vs baseline: 1.2902x; 1.1286x over previous
#include <cuda_runtime.h>
#include <cuda_fp16.h>
#include <cstdint>

#define N_NODES 50000
#define N_EDGES 800000
#define DIM     128
#define N_LAYERS 3
#define N_GRAPHS 128
#define TOT_E   (N_EDGES + N_NODES)   // edges + self loops
#define XS_COLS (DIM * N_LAYERS)      // 384
#define POOL_ELEMS (N_GRAPHS * XS_COLS)
#define NBLK    196                   // ceil(N_NODES/256)

// ---------------- scratch (device globals; no allocation allowed) ----------
__device__ int   g_deg[N_NODES];
__device__ int   g_fill[N_NODES];
__device__ int   g_rowptr[N_NODES + 1];
__device__ int   g_colidx[TOT_E];
__device__ float g_dinv[N_NODES];
__device__ uint2 g_th[(size_t)N_NODES * DIM / 4];  // GEMM output, fp16 (4 halves/elt)
__device__ int   g_goff[N_GRAPHS + 1];
__device__ int   g_bsum[NBLK];

// ---------------- packed f32x2 helpers -------------------------------------
__device__ __forceinline__ unsigned long long pack2(float x, float y) {
    unsigned long long r;
    asm("mov.b64 %0, {%1, %2};" : "=l"(r) : "f"(x), "f"(y));
    return r;
}
__device__ __forceinline__ void unpack2(unsigned long long v, float& lo, float& hi) {
    asm("mov.b64 {%0, %1}, %2;" : "=f"(lo), "=f"(hi) : "l"(v));
}
__device__ __forceinline__ void ffma2(unsigned long long& d,
                                      unsigned long long a,
                                      unsigned long long b) {
    asm("fma.rn.f32x2 %0, %1, %2, %0;" : "+l"(d) : "l"(a), "l"(b));
}

// ---------------- CSR build ------------------------------------------------
__global__ void init_kernel() {
    int n = blockIdx.x * blockDim.x + threadIdx.x;
    if (n < N_NODES) { g_deg[n] = 1; g_fill[n] = 0; }   // self loop counts 1
}

__global__ void edge_deg_kernel(const int* __restrict__ ei) {
    int e = blockIdx.x * blockDim.x + threadIdx.x;
    if (e < N_EDGES) atomicAdd(&g_deg[ei[N_EDGES + e]], 1);
}

// phase A: per-block sums of deg
__global__ void scanA_kernel() {
    __shared__ int sh[8];
    int i = blockIdx.x * 256 + threadIdx.x;
    int v = (i < N_NODES) ? g_deg[i] : 0;
#pragma unroll
    for (int o = 16; o; o >>= 1) v += __shfl_down_sync(~0u, v, o);
    if ((threadIdx.x & 31) == 0) sh[threadIdx.x >> 5] = v;
    __syncthreads();
    if (threadIdx.x < 8) {
        int s = sh[threadIdx.x];
#pragma unroll
        for (int o = 4; o; o >>= 1) s += __shfl_down_sync(0xffu, s, o);
        if (threadIdx.x == 0) g_bsum[blockIdx.x] = s;
    }
}

// phase B: scan the 196 block sums (exclusive, in place); also goff bsearch
__global__ void scanB_kernel(const int* __restrict__ batch) {
    __shared__ int sh[256];
    int t = threadIdx.x;
    int v = (t < NBLK) ? g_bsum[t] : 0;
    sh[t] = v;
    __syncthreads();
#pragma unroll
    for (int o = 1; o < 256; o <<= 1) {
        int u = (t >= o) ? sh[t - o] : 0;
        __syncthreads();
        sh[t] += u;
        __syncthreads();
    }
    if (t < NBLK) g_bsum[t] = sh[t] - v;       // exclusive
    if (t == 0)   g_rowptr[N_NODES] = TOT_E;
    if (t <= N_GRAPHS) {                       // graph offsets
        int lo = 0, hi = N_NODES;
        while (lo < hi) {
            int mid = (lo + hi) >> 1;
            if (batch[mid] < t) lo = mid + 1; else hi = mid;
        }
        g_goff[t] = lo;
    }
}

// phase C: intra-block exclusive scan + base -> rowptr; also dinv
__global__ void scanC_kernel() {
    __shared__ int sh[256];
    int t = threadIdx.x;
    int i = blockIdx.x * 256 + t;
    int v = (i < N_NODES) ? g_deg[i] : 0;
    sh[t] = v;
    __syncthreads();
#pragma unroll
    for (int o = 1; o < 256; o <<= 1) {
        int u = (t >= o) ? sh[t - o] : 0;
        __syncthreads();
        sh[t] += u;
        __syncthreads();
    }
    if (i < N_NODES) {
        g_rowptr[i] = sh[t] - v + g_bsum[blockIdx.x];
        g_dinv[i]   = rsqrtf((float)v);
    }
}

__global__ void fill_kernel(const int* __restrict__ ei) {
    int idx = blockIdx.x * blockDim.x + threadIdx.x;
    if (idx < N_NODES) {                       // self loop
        int pos = g_rowptr[idx] + atomicAdd(&g_fill[idx], 1);
        g_colidx[pos] = idx;
    } else if (idx < N_NODES + N_EDGES) {
        int e = idx - N_NODES;
        int src = ei[e];
        int dst = ei[N_EDGES + e];
        int pos = g_rowptr[dst] + atomicAdd(&g_fill[dst], 1);
        g_colidx[pos] = src;
    }
}

// ---------------- GEMM: T[n,:] = A[n,:] @ W  (f32x2 FFMA, fp16 store) ------
// block: 128 rows x 128 cols, 256 threads, 8x8 per-thread tile, BK=16
__global__ __launch_bounds__(256, 2)
void gemm_kernel(const float* __restrict__ A, int lda,
                 const float* __restrict__ W) {
    __shared__ __align__(16) float As[16][132];
    __shared__ __align__(16) float Ws[16][128];
    const int brow = blockIdx.x * 128;
    const int t  = threadIdx.x;
    const int tx = t & 15;     // col group
    const int ty = t >> 4;     // row group
    unsigned long long acc2[8][4];
#pragma unroll
    for (int i = 0; i < 8; i++)
#pragma unroll
        for (int jp = 0; jp < 4; jp++) acc2[i][jp] = 0ull;

    for (int kc = 0; kc < DIM; kc += 16) {
        // A tile: 128 rows x 16 k, transposed into As[k][row]
#pragma unroll
        for (int i = 0; i < 2; i++) {
            int lin = t + i * 256;          // 0..511
            int row = lin >> 2;             // 0..127
            int kg  = lin & 3;
            float4 v = make_float4(0.f, 0.f, 0.f, 0.f);
            int gr = brow + row;
            if (gr < N_NODES)
                v = *(const float4*)&A[(size_t)gr * lda + kc + kg * 4];
            As[kg * 4 + 0][row] = v.x;
            As[kg * 4 + 1][row] = v.y;
            As[kg * 4 + 2][row] = v.z;
            As[kg * 4 + 3][row] = v.w;
        }
        // W tile: 16 k-rows x 128 cols
#pragma unroll
        for (int i = 0; i < 2; i++) {
            int lin = t + i * 256;
            int kr = lin >> 5;              // 0..15
            int c4 = lin & 31;
            *(float4*)&Ws[kr][c4 * 4] =
                *(const float4*)&W[(kc + kr) * DIM + c4 * 4];
        }
        __syncthreads();
#pragma unroll
        for (int kk = 0; kk < 16; kk++) {
            float a[8];
            unsigned long long w2[4];
#pragma unroll
            for (int i = 0; i < 8; i++) a[i] = As[kk][ty * 8 + i];
#pragma unroll
            for (int jp = 0; jp < 4; jp++)
                w2[jp] = *(const unsigned long long*)&Ws[kk][tx * 8 + jp * 2];
#pragma unroll
            for (int i = 0; i < 8; i++) {
                unsigned long long a2 = pack2(a[i], a[i]);
#pragma unroll
                for (int jp = 0; jp < 4; jp++)
                    ffma2(acc2[i][jp], a2, w2[jp]);
            }
        }
        __syncthreads();
    }
    // epilogue: convert to fp16 and store (dinv applied in SpMM)
#pragma unroll
    for (int i = 0; i < 8; i++) {
        int gr = brow + ty * 8 + i;
        if (gr < N_NODES) {
            float2 f01, f23, f45, f67;
            unpack2(acc2[i][0], f01.x, f01.y);
            unpack2(acc2[i][1], f23.x, f23.y);
            unpack2(acc2[i][2], f45.x, f45.y);
            unpack2(acc2[i][3], f67.x, f67.y);
            __half2 h0 = __float22half2_rn(f01);
            __half2 h1 = __float22half2_rn(f23);
            __half2 h2 = __float22half2_rn(f45);
            __half2 h3 = __float22half2_rn(f67);
            uint4 st;
            st.x = *(unsigned*)&h0;
            st.y = *(unsigned*)&h1;
            st.z = *(unsigned*)&h2;
            st.w = *(unsigned*)&h3;
            // row stride = 32 uint2; this thread covers uint2 slots tx*2, tx*2+1
            *(uint4*)&g_th[(size_t)gr * 32 + tx * 2] = st;
        }
    }
}

// ---- SpMM: out[r,:] = relu(dinv[r]*sum_{s in row r} dinv[s]*T[s,:] + b) ---
// one warp per destination row; gathers fp16 rows (256B each)
__global__ void spmm_kernel(const float* __restrict__ bias,
                            float* __restrict__ out) {
    int w    = (blockIdx.x * blockDim.x + threadIdx.x) >> 5;
    int lane = threadIdx.x & 31;
    if (w >= N_NODES) return;
    int e = g_rowptr[w], end = g_rowptr[w + 1];
    float4 acc = make_float4(0.f, 0.f, 0.f, 0.f);
    for (; e + 1 < end; e += 2) {
        int s0 = g_colidx[e];
        int s1 = g_colidx[e + 1];
        float d0 = __ldg(&g_dinv[s0]);
        float d1 = __ldg(&g_dinv[s1]);
        uint2 u0 = g_th[(size_t)s0 * 32 + lane];
        uint2 u1 = g_th[(size_t)s1 * 32 + lane];
        float2 a0 = __half22float2(*(__half2*)&u0.x);
        float2 b0 = __half22float2(*(__half2*)&u0.y);
        float2 a1 = __half22float2(*(__half2*)&u1.x);
        float2 b1 = __half22float2(*(__half2*)&u1.y);
        acc.x = fmaf(a0.x, d0, fmaf(a1.x, d1, acc.x));
        acc.y = fmaf(a0.y, d0, fmaf(a1.y, d1, acc.y));
        acc.z = fmaf(b0.x, d0, fmaf(b1.x, d1, acc.z));
        acc.w = fmaf(b0.y, d0, fmaf(b1.y, d1, acc.w));
    }
    if (e < end) {
        int s0 = g_colidx[e];
        float d0 = __ldg(&g_dinv[s0]);
        uint2 u0 = g_th[(size_t)s0 * 32 + lane];
        float2 a0 = __half22float2(*(__half2*)&u0.x);
        float2 b0 = __half22float2(*(__half2*)&u0.y);
        acc.x = fmaf(a0.x, d0, acc.x);
        acc.y = fmaf(a0.y, d0, acc.y);
        acc.z = fmaf(b0.x, d0, acc.z);
        acc.w = fmaf(b0.y, d0, acc.w);
    }
    float dv = g_dinv[w];
    float4 bb = *(const float4*)&bias[lane * 4];
    float4 o;
    o.x = fmaxf(fmaf(acc.x, dv, bb.x), 0.f);
    o.y = fmaxf(fmaf(acc.y, dv, bb.y), 0.f);
    o.z = fmaxf(fmaf(acc.z, dv, bb.z), 0.f);
    o.w = fmaxf(fmaf(acc.w, dv, bb.w), 0.f);
    *(float4*)&out[(size_t)w * XS_COLS + lane * 4] = o;
}

// ---------------- pooling: one layer slice (128 cols), block per graph -----
__global__ void pool_kernel(const float* __restrict__ xs_slice,
                            float* __restrict__ pool_slice) {
    int g = blockIdx.x;
    int f = threadIdx.x;      // 0..127
    int s = g_goff[g], e = g_goff[g + 1];
    float sum = 0.f;
    for (int n = s; n < e; n++)
        sum += xs_slice[(size_t)n * XS_COLS + f];
    float cnt = (float)max(e - s, 1);
    pool_slice[(size_t)g * XS_COLS + f] = sum / cnt;
}

// ---------------- launch ---------------------------------------------------
extern "C" void kernel_launch(void* const* d_in, const int* in_sizes, int n_in,
                              void* d_out, int out_size) {
    const float* x     = (const float*)d_in[0];
    const int*   ei    = (const int*)d_in[1];     // int32 (JAX x64 disabled)
    const int*   batch = (const int*)d_in[2];     // int32
    const float* W[3] = { (const float*)d_in[3], (const float*)d_in[5],
                          (const float*)d_in[7] };
    const float* B[3] = { (const float*)d_in[4], (const float*)d_in[6],
                          (const float*)d_in[8] };
    float* out_pool = (float*)d_out;
    float* out_xs   = (float*)d_out + POOL_ELEMS;

    static cudaStream_t s2  = nullptr;
    static cudaEvent_t  evF = nullptr, evJ = nullptr;
    static cudaEvent_t  evS0 = nullptr, evS1 = nullptr, evJ2 = nullptr;
    if (!s2) {
        cudaStreamCreateWithFlags(&s2, cudaStreamNonBlocking);
        cudaEventCreateWithFlags(&evF,  cudaEventDisableTiming);
        cudaEventCreateWithFlags(&evJ,  cudaEventDisableTiming);
        cudaEventCreateWithFlags(&evS0, cudaEventDisableTiming);
        cudaEventCreateWithFlags(&evS1, cudaEventDisableTiming);
        cudaEventCreateWithFlags(&evJ2, cudaEventDisableTiming);
    }

    const int gemm_blocks = (N_NODES + 127) / 128;           // 391
    const int spmm_blocks = (N_NODES * 32 + 255) / 256;

    // fork: layer-0 GEMM (independent of CSR/dinv) runs on s2
    cudaEventRecord(evF, 0);
    cudaStreamWaitEvent(s2, evF, 0);
    gemm_kernel<<<gemm_blocks, 256, 0, s2>>>(x, DIM, W[0]);

    // CSR + norm build on the capture stream
    init_kernel<<<NBLK, 256>>>();
    edge_deg_kernel<<<(N_EDGES + 255) / 256, 256>>>(ei);
    scanA_kernel<<<NBLK, 256>>>();
    scanB_kernel<<<1, 256>>>(batch);
    scanC_kernel<<<NBLK, 256>>>();
    fill_kernel<<<(TOT_E + 255) / 256, 256>>>(ei);

    // join gemm0
    cudaEventRecord(evJ, s2);
    cudaStreamWaitEvent(0, evJ, 0);

    // layer 0
    spmm_kernel<<<spmm_blocks, 256>>>(B[0], out_xs);
    cudaEventRecord(evS0, 0);
    cudaStreamWaitEvent(s2, evS0, 0);
    pool_kernel<<<N_GRAPHS, DIM, 0, s2>>>(out_xs, out_pool);          // overlapped

    // layer 1
    gemm_kernel<<<gemm_blocks, 256>>>(out_xs, XS_COLS, W[1]);
    spmm_kernel<<<spmm_blocks, 256>>>(B[1], out_xs + DIM);
    cudaEventRecord(evS1, 0);
    cudaStreamWaitEvent(s2, evS1, 0);
    pool_kernel<<<N_GRAPHS, DIM, 0, s2>>>(out_xs + DIM, out_pool + DIM); // overlapped

    // layer 2
    gemm_kernel<<<gemm_blocks, 256>>>(out_xs + DIM, XS_COLS, W[2]);
    spmm_kernel<<<spmm_blocks, 256>>>(B[2], out_xs + 2 * DIM);
    pool_kernel<<<N_GRAPHS, DIM>>>(out_xs + 2 * DIM, out_pool + 2 * DIM);

    // join side-stream pools
    cudaEventRecord(evJ2, s2);
    cudaStreamWaitEvent(0, evJ2, 0);
}